// round 16
// baseline (speedup 1.0000x reference)
#include <cuda_runtime.h>

// ---------------- static config ----------------
#define DIMC 256
#define NN   1024      // N*N
#define BATCH 16
#define KH   128       // q channels
#define KU   16        // k channels
#define VU   32        // v channels
#define NKD  16        // DIM_K
#define NHD  8         // HEADS
#define NVD  32        // DIM_V

// ---------------- scratch (device globals; no runtime alloc) ----------------
__device__ float2 g_qraw[BATCH*KH*NN];
__device__ float2 g_kraw[BATCH*KU*NN];
__device__ float2 g_vraw[BATCH*VU*NN];
__device__ float  g_kw  [BATCH*KU*NN];
__device__ float2 g_lamc[BATCH*NKD*NVD];
__device__ float2 g_bng[160];
__device__ float2 g_bnd[160];
__device__ float2 g_Gf[(size_t)NKD*4096];      // FFT of reversed kernels (512 KB)

// compile-time twiddles: w[j] = e^{-2*pi*i*j/64} = (cos, -sin)
__constant__ float2 c_w64[64] = {
    { 1.000000000f, -0.000000000f}, { 0.995184727f, -0.098017140f},
    { 0.980785280f, -0.195090322f}, { 0.956940336f, -0.290284677f},
    { 0.923879533f, -0.382683432f}, { 0.881921264f, -0.471396737f},
    { 0.831469612f, -0.555570233f}, { 0.773010453f, -0.634393284f},
    { 0.707106781f, -0.707106781f}, { 0.634393284f, -0.773010453f},
    { 0.555570233f, -0.831469612f}, { 0.471396737f, -0.881921264f},
    { 0.382683432f, -0.923879533f}, { 0.290284677f, -0.956940336f},
    { 0.195090322f, -0.980785280f}, { 0.098017140f, -0.995184727f},
    { 0.000000000f, -1.000000000f}, {-0.098017140f, -0.995184727f},
    {-0.195090322f, -0.980785280f}, {-0.290284677f, -0.956940336f},
    {-0.382683432f, -0.923879533f}, {-0.471396737f, -0.881921264f},
    {-0.555570233f, -0.831469612f}, {-0.634393284f, -0.773010453f},
    {-0.707106781f, -0.707106781f}, {-0.773010453f, -0.634393284f},
    {-0.831469612f, -0.555570233f}, {-0.881921264f, -0.471396737f},
    {-0.923879533f, -0.382683432f}, {-0.956940336f, -0.290284677f},
    {-0.980785280f, -0.195090322f}, {-0.995184727f, -0.098017140f},
    {-1.000000000f,  0.000000000f}, {-0.995184727f,  0.098017140f},
    {-0.980785280f,  0.195090322f}, {-0.956940336f,  0.290284677f},
    {-0.923879533f,  0.382683432f}, {-0.881921264f,  0.471396737f},
    {-0.831469612f,  0.555570233f}, {-0.773010453f,  0.634393284f},
    {-0.707106781f,  0.707106781f}, {-0.634393284f,  0.773010453f},
    {-0.555570233f,  0.831469612f}, {-0.471396737f,  0.881921264f},
    {-0.382683432f,  0.923879533f}, {-0.290284677f,  0.956940336f},
    {-0.195090322f,  0.980785280f}, {-0.098017140f,  0.995184727f},
    { 0.000000000f,  1.000000000f}, { 0.098017140f,  0.995184727f},
    { 0.195090322f,  0.980785280f}, { 0.290284677f,  0.956940336f},
    { 0.382683432f,  0.923879533f}, { 0.471396737f,  0.881921264f},
    { 0.555570233f,  0.831469612f}, { 0.634393284f,  0.773010453f},
    { 0.707106781f,  0.707106781f}, { 0.773010453f,  0.634393284f},
    { 0.831469612f,  0.555570233f}, { 0.881921264f,  0.471396737f},
    { 0.923879533f,  0.382683432f}, { 0.956940336f,  0.290284677f},
    { 0.980785280f,  0.195090322f}, { 0.995184727f,  0.098017140f}
};

// ---------------- complex helpers ----------------
__device__ __forceinline__ float2 cadd(float2 a, float2 b){ return make_float2(a.x+b.x, a.y+b.y); }
__device__ __forceinline__ float2 csub(float2 a, float2 b){ return make_float2(a.x-b.x, a.y-b.y); }
__device__ __forceinline__ float2 cmul(float2 a, float2 b){ return make_float2(a.x*b.x-a.y*b.y, a.x*b.y+a.y*b.x); }
__device__ __forceinline__ float2 cdivf2(float2 a, float2 b) {
    float d = b.x*b.x + b.y*b.y;
    return make_float2((a.x*b.x + a.y*b.y)/d, (a.y*b.x - a.x*b.y)/d);
}
__device__ __forceinline__ float2 csqrtf2(float2 z) {
    float r = sqrtf(z.x*z.x + z.y*z.y);
    float re = sqrtf(fmaxf(0.f, 0.5f*(r + z.x)));
    float im = sqrtf(fmaxf(0.f, 0.5f*(r - z.x)));
    im = copysignf(im, z.y);
    return make_float2(re, im);
}

// multiply by -i (forward) or +i (inverse)
template<int INV> __device__ __forceinline__ float2 mulJ(float2 z){
    return INV ? make_float2(-z.y, z.x) : make_float2(z.y, -z.x);
}
template<int INV> __device__ __forceinline__ void fft4(float2&a0,float2&a1,float2&a2,float2&a3){
    float2 t0=cadd(a0,a2), t1=csub(a0,a2), t2=cadd(a1,a3), t3=mulJ<INV>(csub(a1,a3));
    a0=cadd(t0,t2); a2=csub(t0,t2); a1=cadd(t1,t3); a3=csub(t1,t3);
}
template<int INV> __device__ __forceinline__ void fft8(float2* a){
    float2 e0=a[0],e1=a[2],e2=a[4],e3=a[6];
    float2 o0=a[1],o1=a[3],o2=a[5],o3=a[7];
    fft4<INV>(e0,e1,e2,e3);
    fft4<INV>(o0,o1,o2,o3);
    const float s = 0.70710678118654752f;
    float2 w1 = INV ? make_float2( s, s) : make_float2( s,-s);
    float2 w3 = INV ? make_float2(-s, s) : make_float2(-s,-s);
    o1 = cmul(o1, w1);
    o2 = mulJ<INV>(o2);
    o3 = cmul(o3, w3);
    a[0]=cadd(e0,o0); a[4]=csub(e0,o0);
    a[1]=cadd(e1,o1); a[5]=csub(e1,o1);
    a[2]=cadd(e2,o2); a[6]=csub(e2,o2);
    a[3]=cadd(e3,o3); a[7]=csub(e3,o3);
}

// 64-point FFT along `base` with given stride. 8 threads per vector (t in [0,8)).
// Radix-8 x radix-8 Cooley-Tukey. `active=false` threads skip work but hit the barrier.
template<int INV>
__device__ __forceinline__ void fft64_pass(float2* base, int stride, int t, bool active) {
    float2 a[8];
    if (active) {
#pragma unroll
        for (int j = 0; j < 8; j++) a[j] = base[(t + 8*j)*stride];
        fft8<INV>(a);
#pragma unroll
        for (int k2 = 1; k2 < 8; k2++) {
            float2 w = c_w64[t*k2];
            if (INV) w.y = -w.y;
            a[k2] = cmul(a[k2], w);
        }
#pragma unroll
        for (int k2 = 0; k2 < 8; k2++) base[(t*8 + k2)*stride] = a[k2];
    }
    __syncthreads();
    if (active) {
#pragma unroll
        for (int n1 = 0; n1 < 8; n1++) a[n1] = base[(n1*8 + t)*stride];
        fft8<INV>(a);
#pragma unroll
        for (int k1 = 0; k1 < 8; k1++) base[(t + 8*k1)*stride] = a[k1];
    }
}

// 2D 64x64 FFT in shared memory, 512 threads. R3-proven mapping (r=tid>>3, t=tid&7).
// mode: 0 = full; 1 = forward-prune (pass 1 only rows r<32 — rest are zero input);
//       2 = inverse-prune (pass 2 only cols r<32 — only those outputs are consumed).
template<int INV>
__device__ __forceinline__ void fft2d_64(float2 (*s)[65], int tid, int mode) {
    int r = tid >> 3, t = tid & 7;
    bool a1 = (mode != 1) || (r < 32);
    bool a2 = (mode != 2) || (r < 32);
    fft64_pass<INV>(&s[r][0], 1, t, a1);      // along second index (within row r)
    __syncthreads();
    fft64_pass<INV>(&s[0][r], 65, t, a2);     // along first index (within column r)
    __syncthreads();
}

// ---------------- fused complex projection: 192 stacked output rows ----------------
// rows 0..127 -> q, 128..143 -> k, 144..175 -> v, 176..191 -> pad (zero)
__device__ __forceinline__ float2 unpack2(unsigned long long v) {
    float2 r;
    asm("mov.b64 {%0,%1}, %2;" : "=f"(r.x), "=f"(r.y) : "l"(v));
    return r;
}
#define FMA2(acc, a, b) asm("fma.rn.f32x2 %0, %1, %2, %0;" : "+l"(acc) : "l"(a), "l"(b))

__global__ __launch_bounds__(256, 3) void proj_kernel(
        const float* __restrict__ Wq_re, const float* __restrict__ Wq_im,
        const float* __restrict__ Wk_re, const float* __restrict__ Wk_im,
        const float* __restrict__ Wv_re, const float* __restrict__ Wv_im,
        const float* __restrict__ Xre, const float* __restrict__ Xim) {
    __shared__ __align__(16) float A_s[16][65][4];  // [cc][o] = {wr,wr,wi,wi}
    __shared__ __align__(16) float B_s[16][65][4];  // [cc][m] = {xr,xi,-xi,xr}

    int tid = threadIdx.x;
    int ty = tid >> 4, tx = tid & 15;
    int m0 = blockIdx.x * 64;
    int o0 = blockIdx.y * 64;
    int b  = blockIdx.z;

    unsigned long long acc[4][4];
#pragma unroll
    for (int i = 0; i < 4; i++)
#pragma unroll
        for (int j = 0; j < 4; j++) acc[i][j] = 0ull;

    for (int c0 = 0; c0 < DIMC; c0 += 16) {
        __syncthreads();
#pragma unroll
        for (int i = 0; i < 4; i++) {
            int e = tid + i*256;
            int cc = e & 15, o = o0 + (e >> 4);
            float wr = 0.f, wi = 0.f;
            if (o < 128)      { int idx = o*DIMC + c0 + cc;        wr = Wq_re[idx]; wi = Wq_im[idx]; }
            else if (o < 144) { int idx = (o-128)*DIMC + c0 + cc;  wr = Wk_re[idx]; wi = Wk_im[idx]; }
            else if (o < 176) { int idx = (o-144)*DIMC + c0 + cc;  wr = Wv_re[idx]; wi = Wv_im[idx]; }
            *(float4*)&A_s[cc][e >> 4][0] = make_float4(wr, wr, wi, wi);
        }
#pragma unroll
        for (int i = 0; i < 4; i++) {
            int e = tid + i*256;
            int m = e & 63, cc = e >> 6;
            int idx = (b*DIMC + c0 + cc)*NN + m0 + m;
            float xr = Xre[idx], xi = Xim[idx];
            *(float4*)&B_s[cc][m][0] = make_float4(xr, xi, -xi, xr);
        }
        __syncthreads();
#pragma unroll
        for (int cc = 0; cc < 16; cc++) {
            ulonglong2 av[4], bv[4];
#pragma unroll
            for (int i = 0; i < 4; i++) av[i] = *(const ulonglong2*)&A_s[cc][ty + 16*i][0];
#pragma unroll
            for (int j = 0; j < 4; j++) bv[j] = *(const ulonglong2*)&B_s[cc][tx + 16*j][0];
#pragma unroll
            for (int i = 0; i < 4; i++)
#pragma unroll
                for (int j = 0; j < 4; j++) {
                    FMA2(acc[i][j], av[i].x, bv[j].x);
                    FMA2(acc[i][j], av[i].y, bv[j].y);
                }
        }
    }
#pragma unroll
    for (int i = 0; i < 4; i++) {
        int o = o0 + ty + 16*i;
        float2* dst = 0;
        size_t row = 0;
        if (o < 128)      { dst = g_qraw; row = (size_t)b*KH + o; }
        else if (o < 144) { dst = g_kraw; row = (size_t)b*KU + (o-128); }
        else if (o < 176) { dst = g_vraw; row = (size_t)b*VU + (o-144); }
        if (dst) {
#pragma unroll
            for (int j = 0; j < 4; j++) {
                int m = m0 + tx + 16*j;
                dst[row*NN + m] = unpack2(acc[i][j]);
            }
        }
    }
}

// ---------------- complex BN stats -> per-channel (g, d): y = x*g + d ----------------
__global__ void bnstats_kernel(const float* __restrict__ qs_re, const float* __restrict__ qs_im,
                               const float* __restrict__ qb_re, const float* __restrict__ qb_im,
                               const float* __restrict__ vs_re, const float* __restrict__ vs_im,
                               const float* __restrict__ vb_re, const float* __restrict__ vb_im) {
    int ch = blockIdx.x;        // 0..127 q, 128..159 v
    int tid = threadIdx.x;
    const float2* data; int C, chl;
    float2 scale, shift;
    if (ch < 128) {
        data = g_qraw; C = KH; chl = ch;
        scale = make_float2(qs_re[chl], qs_im[chl]);
        shift = make_float2(qb_re[chl], qb_im[chl]);
    } else {
        data = g_vraw; C = VU; chl = ch - 128;
        scale = make_float2(vs_re[chl], vs_im[chl]);
        shift = make_float2(vb_re[chl], vb_im[chl]);
    }
    float sr = 0.f, si = 0.f, s2r = 0.f, s2i = 0.f;
    for (int e = tid; e < BATCH*NN; e += 256) {
        int bb = e >> 10, m = e & 1023;
        float2 z = data[((size_t)bb*C + chl)*NN + m];
        sr += z.x; si += z.y;
        s2r += z.x*z.x - z.y*z.y;
        s2i += 2.f*z.x*z.y;
    }
    __shared__ float4 red[256];
    red[tid] = make_float4(sr, si, s2r, s2i);
    __syncthreads();
    for (int s = 128; s > 0; s >>= 1) {
        if (tid < s) {
            float4 a = red[tid], b2 = red[tid + s];
            red[tid] = make_float4(a.x + b2.x, a.y + b2.y, a.z + b2.z, a.w + b2.w);
        }
        __syncthreads();
    }
    if (tid == 0) {
        const float inv = 1.f / (float)(BATCH*NN);
        float4 t = red[0];
        float2 mean = make_float2(t.x*inv, t.y*inv);
        float2 ex2  = make_float2(t.z*inv, t.w*inv);
        float2 var  = make_float2(ex2.x - (mean.x*mean.x - mean.y*mean.y),
                                  ex2.y - 2.f*mean.x*mean.y);
        var.x += 1e-5f;
        float2 s = csqrtf2(var);
        float2 g = cdivf2(scale, s);
        float2 d = make_float2(shift.x - (mean.x*g.x - mean.y*g.y),
                               shift.y - (mean.x*g.y + mean.y*g.x));
        g_bng[ch] = g;
        g_bnd[ch] = d;
    }
}

// ---------------- apply q BN affine in-place (v stays raw; its affine is folded downstream) ----
__global__ void bnqapply_kernel() {
    int e = blockIdx.x * 256 + threadIdx.x;
    if (e >= BATCH*KH*NN) return;
    int ch = (e >> 10) & 127;
    float2 z = g_qraw[e], g = g_bng[ch], d = g_bnd[ch];
    g_qraw[e] = make_float2(z.x*g.x - z.y*g.y + d.x, z.x*g.y + z.y*g.x + d.y);
}

// ---------------- softmax over |k| per (b, kk) row ----------------
__global__ void softmax_kernel() {
    int row = blockIdx.x;   // 0..255
    int tid = threadIdx.x;
    __shared__ float sabs[NN];
    __shared__ float red[256];
    float mx = -1e30f;
    for (int m = tid; m < NN; m += 256) {
        float2 z = g_kraw[(size_t)row*NN + m];
        float a = sqrtf(z.x*z.x + z.y*z.y);
        sabs[m] = a;
        mx = fmaxf(mx, a);
    }
    red[tid] = mx; __syncthreads();
    for (int s = 128; s > 0; s >>= 1) {
        if (tid < s) red[tid] = fmaxf(red[tid], red[tid + s]);
        __syncthreads();
    }
    mx = red[0];
    __syncthreads();
    float sum = 0.f;
    for (int m = tid; m < NN; m += 256) sum += expf(sabs[m] - mx);
    red[tid] = sum; __syncthreads();
    for (int s = 128; s > 0; s >>= 1) {
        if (tid < s) red[tid] += red[tid + s];
        __syncthreads();
    }
    float inv = 1.f / red[0];
    for (int m = tid; m < NN; m += 256)
        g_kw[(size_t)row*NN + m] = expf(sabs[m] - mx) * inv;
}

// ---------------- lam_c[b,kk,v] = sum_m kw[b,kk,m] * (v_raw*g + d) ----------------
// Uses sum_m kw = 1: lam_c = (sum kw*v_raw)*g + d
__global__ void lamc_kernel() {
    int b = blockIdx.x;
    int tid = threadIdx.x;          // 512 threads
    int kk = tid >> 5, v = tid & 31;
    __shared__ float  kw_s[16][128];
    __shared__ float2 v_s[32][129];
    float2 acc = make_float2(0.f, 0.f);
    for (int m0 = 0; m0 < NN; m0 += 128) {
        __syncthreads();
#pragma unroll
        for (int i = 0; i < 4; i++) {
            int e = tid + i*512;
            kw_s[e >> 7][e & 127] = g_kw[((size_t)b*KU + (e >> 7))*NN + m0 + (e & 127)];
        }
#pragma unroll
        for (int i = 0; i < 8; i++) {
            int e = tid + i*512;
            v_s[e >> 7][e & 127] = g_vraw[((size_t)b*VU + (e >> 7))*NN + m0 + (e & 127)];
        }
        __syncthreads();
#pragma unroll 8
        for (int mm = 0; mm < 128; mm++) {
            float w = kw_s[kk][mm];
            float2 vv = v_s[v][mm];
            acc.x += w * vv.x;
            acc.y += w * vv.y;
        }
    }
    float2 g = g_bng[128 + v], d = g_bnd[128 + v];
    float2 r = cadd(cmul(acc, g), d);
    g_lamc[((size_t)b*NKD + kk)*NVD + v] = r;
}

// ---------------- forward FFT of reversed kernels g_k(p) = emb[31-p, k] / 4096 ----------------
__global__ __launch_bounds__(512) void fftg_kernel(const float* __restrict__ er,
                                                   const float* __restrict__ ei) {
    __shared__ float2 s[64][65];
    int k = blockIdx.x;             // 0..15
    int tid = threadIdx.x;
    const float scale = 1.f / 4096.f;
#pragma unroll
    for (int e = tid; e < 4096; e += 512) {
        int r = e >> 6, c = e & 63;
        float2 val = make_float2(0.f, 0.f);
        if (r != 32 && c != 32) {
            int pi = (r <= 31) ? r : r - 64;   // [-31, 31]
            int pj = (c <= 31) ? c : c - 64;
            int di = 31 - pi, dj = 31 - pj;    // [0, 62]
            int idx = (di*63 + dj)*16 + k;
            val = make_float2(er[idx] * scale, ei[idx] * scale);
        }
        s[r][c] = val;
    }
    __syncthreads();
    fft2d_64<0>(s, tid, 0);
#pragma unroll
    for (int e = tid; e < 4096; e += 512) {
        g_Gf[(size_t)k*4096 + e] = s[e >> 6][e & 63];
    }
}

// ---------------- FUSED: v-FFT + per-k iFFT + q-contraction + output ----------------
// One block per (b, vch). Produces out[b, h*32+vch, :] for all h.
// R11-proven structure (Vf in smem, coalesced pointwise loop) + Gf register
// double-buffering: Gf for iteration k+1 is loaded right after the pointwise
// writes of iteration k and consumed one full FFT later, so the pointwise loop
// never exposes global-load latency.
__global__ __launch_bounds__(512) void lampfinal_kernel(float* __restrict__ out, int interleaved) {
    __shared__ float2 s[64][65];      // 33.3 KB workspace
    __shared__ float2 Vf_s[4096];     // 32 KB cached forward FFT of v image
    int bv  = blockIdx.x;             // 0..511
    int b   = bv >> 5, vch = bv & 31;
    int tid = threadIdx.x;

    // load v image (32x32) with BN affine, zero-pad to 64x64
    float2 gv = g_bng[128 + vch], dv = g_bnd[128 + vch];
#pragma unroll
    for (int i = 0; i < 8; i++) {
        int e = tid + i*512;
        int r = e >> 6, c = e & 63;
        float2 val = make_float2(0.f, 0.f);
        if (r < 32 && c < 32) {
            float2 z = g_vraw[(size_t)bv*NN + r*32 + c];
            val = cadd(cmul(z, gv), dv);
        }
        s[r][c] = val;
    }
    __syncthreads();
    fft2d_64<0>(s, tid, 1);           // forward; rows >= 32 are zero -> pruned pass 1

#pragma unroll
    for (int i = 0; i < 8; i++) {
        int e = tid + i*512;
        Vf_s[e] = s[e >> 6][e & 63];
    }

    // prime the Gf register pipeline for k = 0
    float2 Gf_pre[8];
#pragma unroll
    for (int i = 0; i < 8; i++) Gf_pre[i] = g_Gf[tid + i*512];

    int h   = tid >> 6;       // 0..7
    int t64 = tid & 63;       // 0..63
    float2 acc[16];
#pragma unroll
    for (int j = 0; j < 16; j++) acc[j] = make_float2(0.f, 0.f);

    for (int k = 0; k < NKD; k++) {
        __syncthreads();      // protect s from prior reads / Vf_s copy
#pragma unroll
        for (int i = 0; i < 8; i++) {
            int e = tid + i*512;
            s[e >> 6][e & 63] = cmul(Vf_s[e], Gf_pre[i]);
        }
        // prefetch Gf for the next k; completes during the FFT below
        if (k + 1 < NKD) {
            const float2* Gn = g_Gf + (size_t)(k + 1)*4096;
#pragma unroll
            for (int i = 0; i < 8; i++) Gf_pre[i] = Gn[tid + i*512];
        }
        __syncthreads();
        fft2d_64<1>(s, tid, 2);       // inverse; only output cols < 32 consumed -> pruned pass 2

        // ---- contraction: acc_h(n) += q[b, h*16+k](n) * (lam_p(n) + lam_c) ----
        float2 lc = g_lamc[((size_t)b*NKD + k)*NVD + vch];
        const float2* qrow = g_qraw + ((size_t)b*KH + h*16 + k)*NN;   // BN pre-applied
#pragma unroll
        for (int j = 0; j < 16; j++) {
            int n = t64 + 64*j;
            float2 lam = cadd(s[n >> 5][n & 31], lc);
            acc[j] = cadd(acc[j], cmul(qrow[n], lam));
        }
    }

    size_t base = ((size_t)b*256 + h*32 + vch) * NN;
    if (interleaved) {
#pragma unroll
        for (int j = 0; j < 16; j++) ((float2*)out)[base + t64 + 64*j] = acc[j];
    } else {
#pragma unroll
        for (int j = 0; j < 16; j++) out[base + t64 + 64*j] = acc[j].x;
    }
}

// ---------------- launch ----------------
extern "C" void kernel_launch(void* const* d_in, const int* in_sizes, int n_in,
                              void* d_out, int out_size) {
    const float* x_re  = (const float*)d_in[0];
    const float* x_im  = (const float*)d_in[1];
    const float* wq_re = (const float*)d_in[2];
    const float* wq_im = (const float*)d_in[3];
    const float* wk_re = (const float*)d_in[4];
    const float* wk_im = (const float*)d_in[5];
    const float* wv_re = (const float*)d_in[6];
    const float* wv_im = (const float*)d_in[7];
    const float* qs_re = (const float*)d_in[8];
    const float* qs_im = (const float*)d_in[9];
    const float* qb_re = (const float*)d_in[10];
    const float* qb_im = (const float*)d_in[11];
    const float* vs_re = (const float*)d_in[12];
    const float* vs_im = (const float*)d_in[13];
    const float* vb_re = (const float*)d_in[14];
    const float* vb_im = (const float*)d_in[15];
    const float* emb_re = (const float*)d_in[16];
    const float* emb_im = (const float*)d_in[17];

    // fftg first: only needs emb inputs
    fftg_kernel<<<NKD, 512>>>(emb_re, emb_im);

    // fused projection: 192 stacked rows (q|k|v|pad), one launch
    proj_kernel<<<dim3(16, 3, 16), 256>>>(wq_re, wq_im, wk_re, wk_im, wv_re, wv_im, x_re, x_im);

    bnstats_kernel<<<160, 256>>>(qs_re, qs_im, qb_re, qb_im, vs_re, vs_im, vb_re, vb_im);
    bnqapply_kernel<<<(BATCH*KH*NN + 255)/256, 256>>>();
    softmax_kernel<<<BATCH*KU, 256>>>();
    lamc_kernel<<<BATCH, 512>>>();

    const long long TOT = (long long)BATCH * 256 * NN;   // complex elements
    int interleaved = ((long long)out_size >= 2*TOT) ? 1 : 0;
    lampfinal_kernel<<<BATCH*VU, 512>>>((float*)d_out, interleaved);
}

// round 17
// speedup vs baseline: 1.5925x; 1.5925x over previous
#include <cuda_runtime.h>

// ---------------- static config ----------------
#define DIMC 256
#define NN   1024      // N*N
#define BATCH 16
#define KH   128       // q channels
#define KU   16        // k channels
#define VU   32        // v channels
#define NKD  16        // DIM_K
#define NHD  8         // HEADS
#define NVD  32        // DIM_V

// ---------------- scratch (device globals; no runtime alloc) ----------------
__device__ float2 g_qraw[BATCH*KH*NN];
__device__ float2 g_kraw[BATCH*KU*NN];
__device__ float2 g_vraw[BATCH*VU*NN];
__device__ float  g_kw  [BATCH*KU*NN];
__device__ float2 g_lamc[BATCH*NKD*NVD];
__device__ float2 g_bng[160];
__device__ float2 g_bnd[160];
__device__ float2 g_Gf[(size_t)NKD*4096];      // FFT of reversed kernels (512 KB)

// compile-time twiddles: w[j] = e^{-2*pi*i*j/64} = (cos, -sin)
__constant__ float2 c_w64[64] = {
    { 1.000000000f, -0.000000000f}, { 0.995184727f, -0.098017140f},
    { 0.980785280f, -0.195090322f}, { 0.956940336f, -0.290284677f},
    { 0.923879533f, -0.382683432f}, { 0.881921264f, -0.471396737f},
    { 0.831469612f, -0.555570233f}, { 0.773010453f, -0.634393284f},
    { 0.707106781f, -0.707106781f}, { 0.634393284f, -0.773010453f},
    { 0.555570233f, -0.831469612f}, { 0.471396737f, -0.881921264f},
    { 0.382683432f, -0.923879533f}, { 0.290284677f, -0.956940336f},
    { 0.195090322f, -0.980785280f}, { 0.098017140f, -0.995184727f},
    { 0.000000000f, -1.000000000f}, {-0.098017140f, -0.995184727f},
    {-0.195090322f, -0.980785280f}, {-0.290284677f, -0.956940336f},
    {-0.382683432f, -0.923879533f}, {-0.471396737f, -0.881921264f},
    {-0.555570233f, -0.831469612f}, {-0.634393284f, -0.773010453f},
    {-0.707106781f, -0.707106781f}, {-0.773010453f, -0.634393284f},
    {-0.831469612f, -0.555570233f}, {-0.881921264f, -0.471396737f},
    {-0.923879533f, -0.382683432f}, {-0.956940336f, -0.290284677f},
    {-0.980785280f, -0.195090322f}, {-0.995184727f, -0.098017140f},
    {-1.000000000f,  0.000000000f}, {-0.995184727f,  0.098017140f},
    {-0.980785280f,  0.195090322f}, {-0.956940336f,  0.290284677f},
    {-0.923879533f,  0.382683432f}, {-0.881921264f,  0.471396737f},
    {-0.831469612f,  0.555570233f}, {-0.773010453f,  0.634393284f},
    {-0.707106781f,  0.707106781f}, {-0.634393284f,  0.773010453f},
    {-0.555570233f,  0.831469612f}, {-0.471396737f,  0.881921264f},
    {-0.382683432f,  0.923879533f}, {-0.290284677f,  0.956940336f},
    {-0.195090322f,  0.980785280f}, {-0.098017140f,  0.995184727f},
    { 0.000000000f,  1.000000000f}, { 0.098017140f,  0.995184727f},
    { 0.195090322f,  0.980785280f}, { 0.290284677f,  0.956940336f},
    { 0.382683432f,  0.923879533f}, { 0.471396737f,  0.881921264f},
    { 0.555570233f,  0.831469612f}, { 0.634393284f,  0.773010453f},
    { 0.707106781f,  0.707106781f}, { 0.773010453f,  0.634393284f},
    { 0.831469612f,  0.555570233f}, { 0.881921264f,  0.471396737f},
    { 0.923879533f,  0.382683432f}, { 0.956940336f,  0.290284677f},
    { 0.980785280f,  0.195090322f}, { 0.995184727f,  0.098017140f}
};

// ---------------- complex helpers ----------------
__device__ __forceinline__ float2 cadd(float2 a, float2 b){ return make_float2(a.x+b.x, a.y+b.y); }
__device__ __forceinline__ float2 csub(float2 a, float2 b){ return make_float2(a.x-b.x, a.y-b.y); }
__device__ __forceinline__ float2 cmul(float2 a, float2 b){ return make_float2(a.x*b.x-a.y*b.y, a.x*b.y+a.y*b.x); }
__device__ __forceinline__ float2 cdivf2(float2 a, float2 b) {
    float d = b.x*b.x + b.y*b.y;
    return make_float2((a.x*b.x + a.y*b.y)/d, (a.y*b.x - a.x*b.y)/d);
}
__device__ __forceinline__ float2 csqrtf2(float2 z) {
    float r = sqrtf(z.x*z.x + z.y*z.y);
    float re = sqrtf(fmaxf(0.f, 0.5f*(r + z.x)));
    float im = sqrtf(fmaxf(0.f, 0.5f*(r - z.x)));
    im = copysignf(im, z.y);
    return make_float2(re, im);
}

// multiply by -i (forward) or +i (inverse)
template<int INV> __device__ __forceinline__ float2 mulJ(float2 z){
    return INV ? make_float2(-z.y, z.x) : make_float2(z.y, -z.x);
}
template<int INV> __device__ __forceinline__ void fft4(float2&a0,float2&a1,float2&a2,float2&a3){
    float2 t0=cadd(a0,a2), t1=csub(a0,a2), t2=cadd(a1,a3), t3=mulJ<INV>(csub(a1,a3));
    a0=cadd(t0,t2); a2=csub(t0,t2); a1=cadd(t1,t3); a3=csub(t1,t3);
}
template<int INV> __device__ __forceinline__ void fft8(float2* a){
    float2 e0=a[0],e1=a[2],e2=a[4],e3=a[6];
    float2 o0=a[1],o1=a[3],o2=a[5],o3=a[7];
    fft4<INV>(e0,e1,e2,e3);
    fft4<INV>(o0,o1,o2,o3);
    const float s = 0.70710678118654752f;
    float2 w1 = INV ? make_float2( s, s) : make_float2( s,-s);
    float2 w3 = INV ? make_float2(-s, s) : make_float2(-s,-s);
    o1 = cmul(o1, w1);
    o2 = mulJ<INV>(o2);
    o3 = cmul(o3, w3);
    a[0]=cadd(e0,o0); a[4]=csub(e0,o0);
    a[1]=cadd(e1,o1); a[5]=csub(e1,o1);
    a[2]=cadd(e2,o2); a[6]=csub(e2,o2);
    a[3]=cadd(e3,o3); a[7]=csub(e3,o3);
}

// 64-point FFT along `base` with given stride. 8 threads per vector (t in [0,8)).
// Radix-8 x radix-8 Cooley-Tukey. `active=false` threads skip work but hit the barrier.
template<int INV>
__device__ __forceinline__ void fft64_pass(float2* base, int stride, int t, bool active) {
    float2 a[8];
    if (active) {
#pragma unroll
        for (int j = 0; j < 8; j++) a[j] = base[(t + 8*j)*stride];
        fft8<INV>(a);
#pragma unroll
        for (int k2 = 1; k2 < 8; k2++) {
            float2 w = c_w64[t*k2];
            if (INV) w.y = -w.y;
            a[k2] = cmul(a[k2], w);
        }
#pragma unroll
        for (int k2 = 0; k2 < 8; k2++) base[(t*8 + k2)*stride] = a[k2];
    }
    __syncthreads();
    if (active) {
#pragma unroll
        for (int n1 = 0; n1 < 8; n1++) a[n1] = base[(n1*8 + t)*stride];
        fft8<INV>(a);
#pragma unroll
        for (int k1 = 0; k1 < 8; k1++) base[(t + 8*k1)*stride] = a[k1];
    }
}

// 2D 64x64 FFT in shared memory, 512 threads. R3-proven mapping (r=tid>>3, t=tid&7).
// mode: 0 = full; 1 = forward-prune (pass 1 only rows r<32 — rest are zero input);
//       2 = inverse-prune (pass 2 only cols r<32 — only those outputs are consumed).
template<int INV>
__device__ __forceinline__ void fft2d_64(float2 (*s)[65], int tid, int mode) {
    int r = tid >> 3, t = tid & 7;
    bool a1 = (mode != 1) || (r < 32);
    bool a2 = (mode != 2) || (r < 32);
    fft64_pass<INV>(&s[r][0], 1, t, a1);      // along second index (within row r)
    __syncthreads();
    fft64_pass<INV>(&s[0][r], 65, t, a2);     // along first index (within column r)
    __syncthreads();
}

// ---------------- fused complex projection: 192 stacked output rows ----------------
// rows 0..127 -> q, 128..143 -> k, 144..175 -> v, 176..191 -> pad (zero)
__device__ __forceinline__ float2 unpack2(unsigned long long v) {
    float2 r;
    asm("mov.b64 {%0,%1}, %2;" : "=f"(r.x), "=f"(r.y) : "l"(v));
    return r;
}
#define FMA2(acc, a, b) asm("fma.rn.f32x2 %0, %1, %2, %0;" : "+l"(acc) : "l"(a), "l"(b))

__global__ __launch_bounds__(256, 3) void proj_kernel(
        const float* __restrict__ Wq_re, const float* __restrict__ Wq_im,
        const float* __restrict__ Wk_re, const float* __restrict__ Wk_im,
        const float* __restrict__ Wv_re, const float* __restrict__ Wv_im,
        const float* __restrict__ Xre, const float* __restrict__ Xim) {
    __shared__ __align__(16) float A_s[16][65][4];  // [cc][o] = {wr,wr,wi,wi}
    __shared__ __align__(16) float B_s[16][65][4];  // [cc][m] = {xr,xi,-xi,xr}

    int tid = threadIdx.x;
    int ty = tid >> 4, tx = tid & 15;
    int m0 = blockIdx.x * 64;
    int o0 = blockIdx.y * 64;
    int b  = blockIdx.z;

    unsigned long long acc[4][4];
#pragma unroll
    for (int i = 0; i < 4; i++)
#pragma unroll
        for (int j = 0; j < 4; j++) acc[i][j] = 0ull;

    for (int c0 = 0; c0 < DIMC; c0 += 16) {
        __syncthreads();
#pragma unroll
        for (int i = 0; i < 4; i++) {
            int e = tid + i*256;
            int cc = e & 15, o = o0 + (e >> 4);
            float wr = 0.f, wi = 0.f;
            if (o < 128)      { int idx = o*DIMC + c0 + cc;        wr = Wq_re[idx]; wi = Wq_im[idx]; }
            else if (o < 144) { int idx = (o-128)*DIMC + c0 + cc;  wr = Wk_re[idx]; wi = Wk_im[idx]; }
            else if (o < 176) { int idx = (o-144)*DIMC + c0 + cc;  wr = Wv_re[idx]; wi = Wv_im[idx]; }
            *(float4*)&A_s[cc][e >> 4][0] = make_float4(wr, wr, wi, wi);
        }
#pragma unroll
        for (int i = 0; i < 4; i++) {
            int e = tid + i*256;
            int m = e & 63, cc = e >> 6;
            int idx = (b*DIMC + c0 + cc)*NN + m0 + m;
            float xr = Xre[idx], xi = Xim[idx];
            *(float4*)&B_s[cc][m][0] = make_float4(xr, xi, -xi, xr);
        }
        __syncthreads();
#pragma unroll
        for (int cc = 0; cc < 16; cc++) {
            ulonglong2 av[4], bv[4];
#pragma unroll
            for (int i = 0; i < 4; i++) av[i] = *(const ulonglong2*)&A_s[cc][ty + 16*i][0];
#pragma unroll
            for (int j = 0; j < 4; j++) bv[j] = *(const ulonglong2*)&B_s[cc][tx + 16*j][0];
#pragma unroll
            for (int i = 0; i < 4; i++)
#pragma unroll
                for (int j = 0; j < 4; j++) {
                    FMA2(acc[i][j], av[i].x, bv[j].x);
                    FMA2(acc[i][j], av[i].y, bv[j].y);
                }
        }
    }
#pragma unroll
    for (int i = 0; i < 4; i++) {
        int o = o0 + ty + 16*i;
        float2* dst = 0;
        size_t row = 0;
        if (o < 128)      { dst = g_qraw; row = (size_t)b*KH + o; }
        else if (o < 144) { dst = g_kraw; row = (size_t)b*KU + (o-128); }
        else if (o < 176) { dst = g_vraw; row = (size_t)b*VU + (o-144); }
        if (dst) {
#pragma unroll
            for (int j = 0; j < 4; j++) {
                int m = m0 + tx + 16*j;
                dst[row*NN + m] = unpack2(acc[i][j]);
            }
        }
    }
}

// ---------------- complex BN stats -> per-channel (g, d): y = x*g + d ----------------
__global__ void bnstats_kernel(const float* __restrict__ qs_re, const float* __restrict__ qs_im,
                               const float* __restrict__ qb_re, const float* __restrict__ qb_im,
                               const float* __restrict__ vs_re, const float* __restrict__ vs_im,
                               const float* __restrict__ vb_re, const float* __restrict__ vb_im) {
    int ch = blockIdx.x;        // 0..127 q, 128..159 v
    int tid = threadIdx.x;
    const float2* data; int C, chl;
    float2 scale, shift;
    if (ch < 128) {
        data = g_qraw; C = KH; chl = ch;
        scale = make_float2(qs_re[chl], qs_im[chl]);
        shift = make_float2(qb_re[chl], qb_im[chl]);
    } else {
        data = g_vraw; C = VU; chl = ch - 128;
        scale = make_float2(vs_re[chl], vs_im[chl]);
        shift = make_float2(vb_re[chl], vb_im[chl]);
    }
    float sr = 0.f, si = 0.f, s2r = 0.f, s2i = 0.f;
    for (int e = tid; e < BATCH*NN; e += 256) {
        int bb = e >> 10, m = e & 1023;
        float2 z = data[((size_t)bb*C + chl)*NN + m];
        sr += z.x; si += z.y;
        s2r += z.x*z.x - z.y*z.y;
        s2i += 2.f*z.x*z.y;
    }
    __shared__ float4 red[256];
    red[tid] = make_float4(sr, si, s2r, s2i);
    __syncthreads();
    for (int s = 128; s > 0; s >>= 1) {
        if (tid < s) {
            float4 a = red[tid], b2 = red[tid + s];
            red[tid] = make_float4(a.x + b2.x, a.y + b2.y, a.z + b2.z, a.w + b2.w);
        }
        __syncthreads();
    }
    if (tid == 0) {
        const float inv = 1.f / (float)(BATCH*NN);
        float4 t = red[0];
        float2 mean = make_float2(t.x*inv, t.y*inv);
        float2 ex2  = make_float2(t.z*inv, t.w*inv);
        float2 var  = make_float2(ex2.x - (mean.x*mean.x - mean.y*mean.y),
                                  ex2.y - 2.f*mean.x*mean.y);
        var.x += 1e-5f;
        float2 s = csqrtf2(var);
        float2 g = cdivf2(scale, s);
        float2 d = make_float2(shift.x - (mean.x*g.x - mean.y*g.y),
                               shift.y - (mean.x*g.y + mean.y*g.x));
        g_bng[ch] = g;
        g_bnd[ch] = d;
    }
}

// ---------------- apply q BN affine in-place (v stays raw; its affine is folded downstream) ----
__global__ void bnqapply_kernel() {
    int e = blockIdx.x * 256 + threadIdx.x;
    if (e >= BATCH*KH*NN) return;
    int ch = (e >> 10) & 127;
    float2 z = g_qraw[e], g = g_bng[ch], d = g_bnd[ch];
    g_qraw[e] = make_float2(z.x*g.x - z.y*g.y + d.x, z.x*g.y + z.y*g.x + d.y);
}

// ---------------- softmax over |k| per (b, kk) row ----------------
__global__ void softmax_kernel() {
    int row = blockIdx.x;   // 0..255
    int tid = threadIdx.x;
    __shared__ float sabs[NN];
    __shared__ float red[256];
    float mx = -1e30f;
    for (int m = tid; m < NN; m += 256) {
        float2 z = g_kraw[(size_t)row*NN + m];
        float a = sqrtf(z.x*z.x + z.y*z.y);
        sabs[m] = a;
        mx = fmaxf(mx, a);
    }
    red[tid] = mx; __syncthreads();
    for (int s = 128; s > 0; s >>= 1) {
        if (tid < s) red[tid] = fmaxf(red[tid], red[tid + s]);
        __syncthreads();
    }
    mx = red[0];
    __syncthreads();
    float sum = 0.f;
    for (int m = tid; m < NN; m += 256) sum += expf(sabs[m] - mx);
    red[tid] = sum; __syncthreads();
    for (int s = 128; s > 0; s >>= 1) {
        if (tid < s) red[tid] += red[tid + s];
        __syncthreads();
    }
    float inv = 1.f / red[0];
    for (int m = tid; m < NN; m += 256)
        g_kw[(size_t)row*NN + m] = expf(sabs[m] - mx) * inv;
}

// ---------------- lam_c[b,kk,v] = sum_m kw[b,kk,m] * (v_raw*g + d) ----------------
// Uses sum_m kw = 1: lam_c = (sum kw*v_raw)*g + d
__global__ void lamc_kernel() {
    int b = blockIdx.x;
    int tid = threadIdx.x;          // 512 threads
    int kk = tid >> 5, v = tid & 31;
    __shared__ float  kw_s[16][128];
    __shared__ float2 v_s[32][129];
    float2 acc = make_float2(0.f, 0.f);
    for (int m0 = 0; m0 < NN; m0 += 128) {
        __syncthreads();
#pragma unroll
        for (int i = 0; i < 4; i++) {
            int e = tid + i*512;
            kw_s[e >> 7][e & 127] = g_kw[((size_t)b*KU + (e >> 7))*NN + m0 + (e & 127)];
        }
#pragma unroll
        for (int i = 0; i < 8; i++) {
            int e = tid + i*512;
            v_s[e >> 7][e & 127] = g_vraw[((size_t)b*VU + (e >> 7))*NN + m0 + (e & 127)];
        }
        __syncthreads();
#pragma unroll 8
        for (int mm = 0; mm < 128; mm++) {
            float w = kw_s[kk][mm];
            float2 vv = v_s[v][mm];
            acc.x += w * vv.x;
            acc.y += w * vv.y;
        }
    }
    float2 g = g_bng[128 + v], d = g_bnd[128 + v];
    float2 r = cadd(cmul(acc, g), d);
    g_lamc[((size_t)b*NKD + kk)*NVD + v] = r;
}

// ---------------- forward FFT of reversed kernels g_k(p) = emb[31-p, k] / 4096 ----------------
__global__ __launch_bounds__(512) void fftg_kernel(const float* __restrict__ er,
                                                   const float* __restrict__ ei) {
    __shared__ float2 s[64][65];
    int k = blockIdx.x;             // 0..15
    int tid = threadIdx.x;
    const float scale = 1.f / 4096.f;
#pragma unroll
    for (int e = tid; e < 4096; e += 512) {
        int r = e >> 6, c = e & 63;
        float2 val = make_float2(0.f, 0.f);
        if (r != 32 && c != 32) {
            int pi = (r <= 31) ? r : r - 64;   // [-31, 31]
            int pj = (c <= 31) ? c : c - 64;
            int di = 31 - pi, dj = 31 - pj;    // [0, 62]
            int idx = (di*63 + dj)*16 + k;
            val = make_float2(er[idx] * scale, ei[idx] * scale);
        }
        s[r][c] = val;
    }
    __syncthreads();
    fft2d_64<0>(s, tid, 0);
#pragma unroll
    for (int e = tid; e < 4096; e += 512) {
        g_Gf[(size_t)k*4096 + e] = s[e >> 6][e & 63];
    }
}

// ---------------- FUSED: v-FFT + per-k iFFT + q-contraction + output ----------------
// One block per (b, vch). Produces out[b, h*32+vch, :] for all h.
__global__ __launch_bounds__(512, 2) void lampfinal_kernel(float* __restrict__ out, int interleaved) {
    __shared__ float2 s[64][65];      // 33.3 KB workspace
    __shared__ float2 Vf_s[4096];     // 32 KB cached forward FFT of v image
    int bv  = blockIdx.x;             // 0..511
    int b   = bv >> 5, vch = bv & 31;
    int tid = threadIdx.x;

    // load v image (32x32) with BN affine, zero-pad to 64x64
    float2 gv = g_bng[128 + vch], dv = g_bnd[128 + vch];
#pragma unroll
    for (int i = 0; i < 8; i++) {
        int e = tid + i*512;
        int r = e >> 6, c = e & 63;
        float2 val = make_float2(0.f, 0.f);
        if (r < 32 && c < 32) {
            float2 z = g_vraw[(size_t)bv*NN + r*32 + c];
            val = cadd(cmul(z, gv), dv);
        }
        s[r][c] = val;
    }
    __syncthreads();
    fft2d_64<0>(s, tid, 1);           // forward; rows >= 32 are zero -> pruned pass 1

#pragma unroll
    for (int i = 0; i < 8; i++) {
        int e = tid + i*512;
        Vf_s[e] = s[e >> 6][e & 63];
    }

    int h   = tid >> 6;       // 0..7
    int t64 = tid & 63;       // 0..63
    float2 acc[16];
#pragma unroll
    for (int j = 0; j < 16; j++) acc[j] = make_float2(0.f, 0.f);

    for (int k = 0; k < NKD; k++) {
        __syncthreads();      // protect s from prior reads / Vf_s copy
        const float2* Gf = g_Gf + (size_t)k*4096;
#pragma unroll
        for (int i = 0; i < 8; i++) {
            int e = tid + i*512;
            s[e >> 6][e & 63] = cmul(Vf_s[e], Gf[e]);
        }
        __syncthreads();
        fft2d_64<1>(s, tid, 2);       // inverse; only output cols < 32 consumed -> pruned pass 2

        // ---- contraction: acc_h(n) += q[b, h*16+k](n) * (lam_p(n) + lam_c) ----
        float2 lc = g_lamc[((size_t)b*NKD + k)*NVD + vch];
        const float2* qrow = g_qraw + ((size_t)b*KH + h*16 + k)*NN;   // BN pre-applied
#pragma unroll
        for (int j = 0; j < 16; j++) {
            int n = t64 + 64*j;
            float2 lam = cadd(s[n >> 5][n & 31], lc);
            acc[j] = cadd(acc[j], cmul(qrow[n], lam));
        }
    }

    size_t base = ((size_t)b*256 + h*32 + vch) * NN;
    if (interleaved) {
#pragma unroll
        for (int j = 0; j < 16; j++) ((float2*)out)[base + t64 + 64*j] = acc[j];
    } else {
#pragma unroll
        for (int j = 0; j < 16; j++) out[base + t64 + 64*j] = acc[j].x;
    }
}

// ---------------- launch ----------------
extern "C" void kernel_launch(void* const* d_in, const int* in_sizes, int n_in,
                              void* d_out, int out_size) {
    const float* x_re  = (const float*)d_in[0];
    const float* x_im  = (const float*)d_in[1];
    const float* wq_re = (const float*)d_in[2];
    const float* wq_im = (const float*)d_in[3];
    const float* wk_re = (const float*)d_in[4];
    const float* wk_im = (const float*)d_in[5];
    const float* wv_re = (const float*)d_in[6];
    const float* wv_im = (const float*)d_in[7];
    const float* qs_re = (const float*)d_in[8];
    const float* qs_im = (const float*)d_in[9];
    const float* qb_re = (const float*)d_in[10];
    const float* qb_im = (const float*)d_in[11];
    const float* vs_re = (const float*)d_in[12];
    const float* vs_im = (const float*)d_in[13];
    const float* vb_re = (const float*)d_in[14];
    const float* vb_im = (const float*)d_in[15];
    const float* emb_re = (const float*)d_in[16];
    const float* emb_im = (const float*)d_in[17];

    // fftg first: only needs emb inputs
    fftg_kernel<<<NKD, 512>>>(emb_re, emb_im);

    // fused projection: 192 stacked rows (q|k|v|pad), one launch
    proj_kernel<<<dim3(16, 3, 16), 256>>>(wq_re, wq_im, wk_re, wk_im, wv_re, wv_im, x_re, x_im);

    bnstats_kernel<<<160, 256>>>(qs_re, qs_im, qb_re, qb_im, vs_re, vs_im, vb_re, vb_im);
    bnqapply_kernel<<<(BATCH*KH*NN + 255)/256, 256>>>();
    softmax_kernel<<<BATCH*KU, 256>>>();
    lamc_kernel<<<BATCH, 512>>>();

    const long long TOT = (long long)BATCH * 256 * NN;   // complex elements
    int interleaved = ((long long)out_size >= 2*TOT) ? 1 : 0;
    lampfinal_kernel<<<BATCH*VU, 512>>>((float*)d_out, interleaved);
}